// round 13
// baseline (speedup 1.0000x reference)
#include <cuda_runtime.h>
#include <cuda_bf16.h>

// Problem constants
#define B_TOT   32768
#define NPER    960        // 120*4*2
#define P1N     240
#define P2N     80
#define NLATENT 100
#define GRID_P  1036       // 148 SMs * 7 resident blocks

// Output layout (float elements):
//   z[B,100] | aug_xm[B,960] | aug_x_sd[B,1] | pool1_idx[B,240] | pool2_idx[B,80]
#define OFF_Z   ((size_t)0)
#define OFF_AXM ((size_t)B_TOT * NLATENT)
#define OFF_ASD (OFF_AXM + (size_t)B_TOT * NPER)
#define OFF_P1  (OFF_ASD + (size_t)B_TOT)
#define OFF_P2  (OFF_P1  + (size_t)B_TOT * P1N)

typedef unsigned long long u64;

// Consolidated constant bank: packed {w,w} conv weights + {b,b} biases.
struct __align__(16) CParams {
    u64 w1p[21];
    u64 w2p[21];
    u64 bb[2];
};
__constant__ CParams c_p;

// Staging buffer written by prep_kernel, copied to c_p by ONE memcpy node.
__device__ u64   g_stage[44];
// Pre-swizzled GEMV weights (loaded ONCE per persistent block into registers)
__device__ float g_fm1X[800];    // [i<10][t<80] = fcm1_w[(t>>3)*80 + (t&7) + 8i]
__device__ float g_fcX[1100];    // [k<11][t<100] = fc_w[t*11 + k]

static __device__ __forceinline__ u64 pk2(float x, float y) {
    u64 r; asm("mov.b64 %0, {%1, %2};" : "=l"(r) : "f"(x), "f"(y)); return r;
}
static __device__ __forceinline__ void upk2(u64 v, float& x, float& y) {
    asm("mov.b64 {%0, %1}, %2;" : "=f"(x), "=f"(y) : "l"(v));
}
static __device__ __forceinline__ u64 ffma2(u64 a, u64 b, u64 c) {
    u64 d; asm("fma.rn.f32x2 %0, %1, %2, %3;" : "=l"(d) : "l"(a), "l"(b), "l"(c));
    return d;
}
// XOR swizzle on 16B-group index: spreads depth-strided accesses over bank groups
static __device__ __forceinline__ int SWZ(int g) { return g ^ ((g >> 3) & 7); }

__global__ void prep_kernel(const float* __restrict__ w1, const float* __restrict__ b1,
                            const float* __restrict__ w2, const float* __restrict__ b2,
                            const float* __restrict__ fcm1_w,
                            const float* __restrict__ fc_w) {
    const int t = threadIdx.x;
    if (t < 21) {
        float a = w1[t]; g_stage[t]      = pk2(a, a);
        float c = w2[t]; g_stage[21 + t] = pk2(c, c);
    }
    if (t == 32) { float v = b1[0]; g_stage[42] = pk2(v, v); }
    if (t == 33) { float v = b2[0]; g_stage[43] = pk2(v, v); }
    for (int idx = t; idx < 800; idx += 128) {
        int i = idx / 80, r = idx - i * 80;
        int j = r >> 3, s = r & 7;
        g_fm1X[idx] = fcm1_w[j * 80 + s + 8 * i];
    }
    for (int idx = t; idx < 1100; idx += 128) {
        int k = idx / 100, j = idx - k * 100;
        g_fcX[idx] = fc_w[j * 11 + k];
    }
}

__global__ __launch_bounds__(128, 7)
void enc_kernel(const float* __restrict__ x1, const float* __restrict__ x2,
                const float* __restrict__ fcm1_b, const float* __restrict__ fc_b,
                float* __restrict__ out)
{
    // Rows of 8 floats (= 2 float4 groups), depth-halo of 3 zero rows each side.
    // Row r: group 2r = {h0w0,h0w1,h1w0,h1w1}, group 2r+1 = {h2w0,h2w1,h3w0,h3w1}.
    __shared__ float4 xsh4[256];   // 126 rows (d+3 in 0..125) -> groups 0..251 (+swizzle pad)
    __shared__ float4 p1sh4[72];   // 36 rows  (d+3 in 0..35)  -> groups 0..71
    __shared__ float  p2v[P2N];
    __shared__ float  vec[11];     // [0..9]=ELU(fcm1), [10]=sigmoid(x2)

    const int tid = threadIdx.x;

    // ======= once-per-persistent-block: weights -> registers, halos -> 0 =======
    float wF[11], bF = 0.0f;       // phase F weights/bias (tid<100)
    float wE[10], bE = 0.0f;       // phase E weights (tid<80), bias at s==0
    if (tid < NLATENT) {
        #pragma unroll
        for (int k = 0; k < 11; k++) wF[k] = g_fcX[k * 100 + tid];
        bF = fc_b[tid];
    }
    if (tid < 80) {
        #pragma unroll
        for (int i = 0; i < 10; i++) wE[i] = g_fm1X[80 * i + tid];
        if ((tid & 7) == 0) bE = fcm1_b[tid >> 3];
    }
    if (tid < 12) {      // zero depth-halo rows once (never overwritten by data)
        int g = (tid < 6) ? tid : (240 + tid);
        xsh4[SWZ(g)] = make_float4(0.f, 0.f, 0.f, 0.f);
        p1sh4[SWZ((tid < 6) ? tid : (60 + tid))] = make_float4(0.f, 0.f, 0.f, 0.f);
    }

    for (int b = blockIdx.x; b < B_TOT; b += GRID_P) {

        // ---------------- Phase A: input staging + fused aug copies ----------------
        const float4* xin = (const float4*)(x1 + (size_t)b * NPER);
        float4*       axm = (float4*)(out + OFF_AXM + (size_t)b * NPER);
        {
            float4 v = xin[tid];
            axm[tid] = v;                           // aug_xm = x1 (eval identity)
            xsh4[SWZ(tid + 6)] = v;                 // group g = i + 6
        }
        if (tid < 112) {
            int i = tid + 128;
            float4 v = xin[i];
            axm[i] = v;
            xsh4[SWZ(i + 6)] = v;
        }
        if (tid == 120) {
            float xv = x2[b];
            out[OFF_ASD + b] = xv;                  // aug_x_sd = x2
            vec[10] = 1.0f / (1.0f + expf(-xv));
        }
        __syncthreads();

        // ------- Phase B: conv1(7,3,1)+ReLU+maxpool4+argmax, hp warp-specialized -------
        // warp0: hp=0 (outputs h=0,1); warp1: hp=1 (outputs h=2,3); dp = lane (0..29)
        if (tid < 64) {
            const int hp = tid >> 5;
            const int dp = tid & 31;
            if (dp < 30) {
                u64 acc[4][2];
                {
                    u64 bi = c_p.bb[0];
                    #pragma unroll
                    for (int j = 0; j < 4; j++) { acc[j][0] = bi; acc[j][1] = bi; }
                }
                if (hp == 0) {        // warp-uniform branch, no divergence
                    #pragma unroll
                    for (int kd = 0; kd < 10; kd++) {
                        const int r = 4 * dp + kd;
                        ulonglong2 A = *(const ulonglong2*)&xsh4[SWZ(2 * r)];       // h0,h1
                        u64        Bx = *(const u64*)&xsh4[SWZ(2 * r + 1)];         // h2
                        #pragma unroll
                        for (int j = 0; j < 4; j++) {
                            const int a = kd - j;
                            if (a < 0 || a > 6) continue;
                            acc[j][0] = ffma2(A.x, c_p.w1p[a * 3 + 1], acc[j][0]);
                            acc[j][0] = ffma2(A.y, c_p.w1p[a * 3 + 2], acc[j][0]);
                            acc[j][1] = ffma2(A.x, c_p.w1p[a * 3 + 0], acc[j][1]);
                            acc[j][1] = ffma2(A.y, c_p.w1p[a * 3 + 1], acc[j][1]);
                            acc[j][1] = ffma2(Bx,  c_p.w1p[a * 3 + 2], acc[j][1]);
                        }
                    }
                } else {
                    #pragma unroll
                    for (int kd = 0; kd < 10; kd++) {
                        const int r = 4 * dp + kd;
                        u64        Ay = ((const u64*)&xsh4[SWZ(2 * r)])[1];          // h1
                        ulonglong2 Bv = *(const ulonglong2*)&xsh4[SWZ(2 * r + 1)];   // h2,h3
                        #pragma unroll
                        for (int j = 0; j < 4; j++) {
                            const int a = kd - j;
                            if (a < 0 || a > 6) continue;
                            acc[j][0] = ffma2(Ay,   c_p.w1p[a * 3 + 0], acc[j][0]);
                            acc[j][0] = ffma2(Bv.x, c_p.w1p[a * 3 + 1], acc[j][0]);
                            acc[j][0] = ffma2(Bv.y, c_p.w1p[a * 3 + 2], acc[j][0]);
                            acc[j][1] = ffma2(Bv.x, c_p.w1p[a * 3 + 0], acc[j][1]);
                            acc[j][1] = ffma2(Bv.y, c_p.w1p[a * 3 + 1], acc[j][1]);
                        }
                    }
                }
                float bv0 = -1.f, bv1 = -1.f, bv2 = -1.f, bv3 = -1.f;
                float bj0 = 0.f, bj1 = 0.f, bj2 = 0.f, bj3 = 0.f;   // best j as float
                #pragma unroll
                for (int j = 0; j < 4; j++) {
                    const float fj = (float)j;
                    float p00, p01, p10, p11, v;
                    upk2(acc[j][0], p00, p01); upk2(acc[j][1], p10, p11);
                    v = fmaxf(p00, 0.f); if (v > bv0) { bv0 = v; bj0 = fj; }  // strict > = first-max
                    v = fmaxf(p01, 0.f); if (v > bv1) { bv1 = v; bj1 = fj; }
                    v = fmaxf(p10, 0.f); if (v > bv2) { bv2 = v; bj2 = fj; }
                    v = fmaxf(p11, 0.f); if (v > bv3) { bv3 = v; bj3 = fj; }
                }
                p1sh4[SWZ(2 * (dp + 3) + hp)] = make_float4(bv0, bv1, bv2, bv3);
                // index = ((4dp+bj)*4 + h)*2 + w = base + bj*8
                const float cb = (float)(((4 * dp) * 4 + 2 * hp) * 2);
                float4 iv;
                iv.x = fmaf(bj0, 8.f, cb);
                iv.y = fmaf(bj1, 8.f, cb + 1.f);
                iv.z = fmaf(bj2, 8.f, cb + 2.f);
                iv.w = fmaf(bj3, 8.f, cb + 3.f);
                *(float4*)&out[OFF_P1 + (size_t)b * P1N + dp * 8 + hp * 4] = iv;
            }
        }
        __syncthreads();

        // ------- Phase C: conv2(7,3,1)+ReLU+maxpool3+argmax, hp warp-specialized -------
        if (tid < 64) {
            const int hp = tid >> 5;
            const int dp = tid & 31;
            if (dp < 10) {
                u64 acc[3][2];
                {
                    u64 bi = c_p.bb[1];
                    #pragma unroll
                    for (int j = 0; j < 3; j++) { acc[j][0] = bi; acc[j][1] = bi; }
                }
                if (hp == 0) {
                    #pragma unroll
                    for (int t = 0; t < 9; t++) {
                        const int r = 3 * dp + t;
                        ulonglong2 A = *(const ulonglong2*)&p1sh4[SWZ(2 * r)];
                        u64        Bx = *(const u64*)&p1sh4[SWZ(2 * r + 1)];
                        #pragma unroll
                        for (int j = 0; j < 3; j++) {
                            const int a = t - j;
                            if (a < 0 || a > 6) continue;
                            acc[j][0] = ffma2(A.x, c_p.w2p[a * 3 + 1], acc[j][0]);
                            acc[j][0] = ffma2(A.y, c_p.w2p[a * 3 + 2], acc[j][0]);
                            acc[j][1] = ffma2(A.x, c_p.w2p[a * 3 + 0], acc[j][1]);
                            acc[j][1] = ffma2(A.y, c_p.w2p[a * 3 + 1], acc[j][1]);
                            acc[j][1] = ffma2(Bx,  c_p.w2p[a * 3 + 2], acc[j][1]);
                        }
                    }
                } else {
                    #pragma unroll
                    for (int t = 0; t < 9; t++) {
                        const int r = 3 * dp + t;
                        u64        Ay = ((const u64*)&p1sh4[SWZ(2 * r)])[1];
                        ulonglong2 Bv = *(const ulonglong2*)&p1sh4[SWZ(2 * r + 1)];
                        #pragma unroll
                        for (int j = 0; j < 3; j++) {
                            const int a = t - j;
                            if (a < 0 || a > 6) continue;
                            acc[j][0] = ffma2(Ay,   c_p.w2p[a * 3 + 0], acc[j][0]);
                            acc[j][0] = ffma2(Bv.x, c_p.w2p[a * 3 + 1], acc[j][0]);
                            acc[j][0] = ffma2(Bv.y, c_p.w2p[a * 3 + 2], acc[j][0]);
                            acc[j][1] = ffma2(Bv.x, c_p.w2p[a * 3 + 0], acc[j][1]);
                            acc[j][1] = ffma2(Bv.y, c_p.w2p[a * 3 + 1], acc[j][1]);
                        }
                    }
                }
                float bv0 = -1.f, bv1 = -1.f, bv2 = -1.f, bv3 = -1.f;
                float bj0 = 0.f, bj1 = 0.f, bj2 = 0.f, bj3 = 0.f;
                #pragma unroll
                for (int j = 0; j < 3; j++) {
                    const float fj = (float)j;
                    float p00, p01, p10, p11, v;
                    upk2(acc[j][0], p00, p01); upk2(acc[j][1], p10, p11);
                    v = fmaxf(p00, 0.f); if (v > bv0) { bv0 = v; bj0 = fj; }
                    v = fmaxf(p01, 0.f); if (v > bv1) { bv1 = v; bj1 = fj; }
                    v = fmaxf(p10, 0.f); if (v > bv2) { bv2 = v; bj2 = fj; }
                    v = fmaxf(p11, 0.f); if (v > bv3) { bv3 = v; bj3 = fj; }
                }
                *(float4*)&p2v[dp * 8 + hp * 4] = make_float4(bv0, bv1, bv2, bv3);
                const float cb = (float)(((3 * dp) * 4 + 2 * hp) * 2);
                float4 iv;
                iv.x = fmaf(bj0, 8.f, cb);
                iv.y = fmaf(bj1, 8.f, cb + 1.f);
                iv.z = fmaf(bj2, 8.f, cb + 2.f);
                iv.w = fmaf(bj3, 8.f, cb + 3.f);
                *(float4*)&out[OFF_P2 + (size_t)b * P2N + dp * 8 + hp * 4] = iv;
            }
        }
        __syncthreads();

        // ------- Phase E: fcm1 (80->10) + ELU, 8 lanes/output, reg-resident weights -------
        if (tid < 80) {
            const int s = tid & 7;
            float acc = 0.0f;
            #pragma unroll
            for (int i = 0; i < 10; i++)
                acc = fmaf(p2v[s + 8 * i], wE[i], acc);     // LDS broadcast groups
            unsigned m = __activemask();
            acc += __shfl_xor_sync(m, acc, 4);
            acc += __shfl_xor_sync(m, acc, 2);
            acc += __shfl_xor_sync(m, acc, 1);
            if (s == 0) {
                float t = acc + bE;
                vec[tid >> 3] = (t > 0.0f) ? t : expm1f(t);
            }
        }
        __syncthreads();

        // ------- Phase F: fc (11->100) + BatchNorm eval, reg-resident weights -------
        if (tid < NLATENT) {
            float acc = bF;
            #pragma unroll
            for (int k = 0; k < 11; k++)
                acc = fmaf(vec[k], wF[k], acc);
            out[OFF_Z + (size_t)b * NLATENT + tid] = acc * 0.9999950000374996f;
        }
        __syncthreads();   // protect vec/xsh4 from next iteration's Phase A
    }
}

extern "C" void kernel_launch(void* const* d_in, const int* in_sizes, int n_in,
                              void* d_out, int out_size)
{
    const float* x1     = (const float*)d_in[0];
    const float* x2     = (const float*)d_in[1];
    // d_in[2]=shifts, d_in[3]=nonzero_mask_xm : unused in eval-mode forward
    const float* w1     = (const float*)d_in[4];
    const float* b1     = (const float*)d_in[5];
    const float* w2     = (const float*)d_in[6];
    const float* b2     = (const float*)d_in[7];
    const float* fcm1_w = (const float*)d_in[8];
    const float* fcm1_b = (const float*)d_in[9];
    const float* fc_w   = (const float*)d_in[10];
    const float* fc_b   = (const float*)d_in[11];
    float* out = (float*)d_out;

    prep_kernel<<<1, 128>>>(w1, b1, w2, b2, fcm1_w, fc_w);

    // ONE consolidated D2D memcpy node: staging -> constant bank
    void* stage_ptr = nullptr;
    cudaGetSymbolAddress(&stage_ptr, g_stage);        // host-side lookup, no alloc
    cudaMemcpyToSymbolAsync(c_p, stage_ptr, sizeof(CParams), 0,
                            cudaMemcpyDeviceToDevice, 0);

    enc_kernel<<<GRID_P, 128>>>(x1, x2, fcm1_b, fc_b, out);
}

// round 14
// speedup vs baseline: 1.3512x; 1.3512x over previous
#include <cuda_runtime.h>
#include <cuda_bf16.h>

// Problem constants
#define B_TOT   32768
#define NPER    960        // 120*4*2
#define P1N     240
#define P2N     80
#define NLATENT 100

// Output layout (float elements):
//   z[B,100] | aug_xm[B,960] | aug_x_sd[B,1] | pool1_idx[B,240] | pool2_idx[B,80]
#define OFF_Z   ((size_t)0)
#define OFF_AXM ((size_t)B_TOT * NLATENT)
#define OFF_ASD (OFF_AXM + (size_t)B_TOT * NPER)
#define OFF_P1  (OFF_ASD + (size_t)B_TOT)
#define OFF_P2  (OFF_P1  + (size_t)B_TOT * P1N)

typedef unsigned long long u64;

// Consolidated constant bank: packed {w,w} conv weights + {b,b} biases.
struct __align__(16) CParams {
    u64 w1p[21];
    u64 w2p[21];
    u64 bb[2];
};
__constant__ CParams c_p;

// Staging buffer written by prep_kernel, copied to c_p by ONE memcpy node.
__device__ u64   g_stage[44];
// Pre-swizzled GEMV weights
__device__ float g_fm1Y[800];    // [i<20][t<40] = fcm1_w[(t>>2)*80 + (t&3) + 4i]
__device__ float g_fcX[1100];    // [k<11][t<100] = fc_w[t*11 + k]

static __device__ __forceinline__ u64 pk2(float x, float y) {
    u64 r; asm("mov.b64 %0, {%1, %2};" : "=l"(r) : "f"(x), "f"(y)); return r;
}
static __device__ __forceinline__ void upk2(u64 v, float& x, float& y) {
    asm("mov.b64 {%0, %1}, %2;" : "=f"(x), "=f"(y) : "l"(v));
}
static __device__ __forceinline__ u64 ffma2(u64 a, u64 b, u64 c) {
    u64 d; asm("fma.rn.f32x2 %0, %1, %2, %3;" : "=l"(d) : "l"(a), "l"(b), "l"(c));
    return d;
}
// XOR swizzle on 16B-group index: spreads depth-strided accesses over bank groups
static __device__ __forceinline__ int SWZ(int g) { return g ^ ((g >> 3) & 7); }

__global__ void prep_kernel(const float* __restrict__ w1, const float* __restrict__ b1,
                            const float* __restrict__ w2, const float* __restrict__ b2,
                            const float* __restrict__ fcm1_w,
                            const float* __restrict__ fc_w) {
    const int t = threadIdx.x;
    if (t < 21) {
        float a = w1[t]; g_stage[t]      = pk2(a, a);
        float c = w2[t]; g_stage[21 + t] = pk2(c, c);
    }
    if (t == 32) { float v = b1[0]; g_stage[42] = pk2(v, v); }
    if (t == 33) { float v = b2[0]; g_stage[43] = pk2(v, v); }
    for (int idx = t; idx < 800; idx += 128) {
        int i = idx / 40, r = idx - i * 40;       // i<20, r = j*4+s
        int j = r >> 2, s = r & 3;
        g_fm1Y[idx] = fcm1_w[j * 80 + s + 4 * i];
    }
    for (int idx = t; idx < 1100; idx += 128) {
        int k = idx / 100, j = idx - k * 100;
        g_fcX[idx] = fc_w[j * 11 + k];
    }
}

__global__ __launch_bounds__(64, 16)
void enc_kernel(const float* __restrict__ x1, const float* __restrict__ x2,
                const float* __restrict__ fcm1_b, const float* __restrict__ fc_b,
                float* __restrict__ out)
{
    // Rows of 8 floats (= 2 float4 groups), depth-halo of 3 zero rows each side.
    // Row r: group 2r = {h0w0,h0w1,h1w0,h1w1}, group 2r+1 = {h2w0,h2w1,h3w0,h3w1}.
    __shared__ float4 xsh4[256];   // 126 rows (d+3 in 0..125) -> groups 0..251 (+swizzle pad)
    __shared__ float4 p1sh4[72];   // 36 rows  (d+3 in 0..35)  -> groups 0..71
    __shared__ float  p2v[P2N];
    __shared__ float  vec[11];     // [0..9]=ELU(fcm1), [10]=sigmoid(x2)

    const int tid = threadIdx.x;
    const int b   = blockIdx.x;

    // ---------------- Phase A: input staging + fused aug copies ----------------
    if (tid < 12) {      // zero depth-halo rows (groups 0..5 and 246..251)
        int g = (tid < 6) ? tid : (240 + tid);
        xsh4[SWZ(g)] = make_float4(0.f, 0.f, 0.f, 0.f);
        p1sh4[SWZ((tid < 6) ? tid : (60 + tid))] = make_float4(0.f, 0.f, 0.f, 0.f);
    }
    const float4* xin = (const float4*)(x1 + (size_t)b * NPER);
    float4*       axm = (float4*)(out + OFF_AXM + (size_t)b * NPER);
    #pragma unroll
    for (int k = 0; k < 4; k++) {
        int i = tid + 64 * k;
        if (k < 3 || tid < 48) {                    // 240 groups total
            float4 v = xin[i];
            axm[i] = v;                             // aug_xm = x1 (eval identity)
            xsh4[SWZ(i + 6)] = v;                   // group g = i + 6
        }
    }
    if (tid == 63) {
        float xv = x2[b];
        out[OFF_ASD + b] = xv;                      // aug_x_sd = x2
        vec[10] = 1.0f / (1.0f + expf(-xv));
    }
    __syncthreads();

    // ------- Phase B: conv1(7,3,1)+ReLU+maxpool4+argmax, hp warp-specialized -------
    // warp0: hp=0 (outputs h=0,1); warp1: hp=1 (outputs h=2,3); dp = lane (0..29)
    {
        const int hp = tid >> 5;
        const int dp = tid & 31;
        if (dp < 30) {
            u64 acc[4][2];
            {
                u64 bi = c_p.bb[0];
                #pragma unroll
                for (int j = 0; j < 4; j++) { acc[j][0] = bi; acc[j][1] = bi; }
            }
            if (hp == 0) {        // warp-uniform branch, no divergence
                #pragma unroll
                for (int kd = 0; kd < 10; kd++) {
                    const int r = 4 * dp + kd;
                    ulonglong2 A = *(const ulonglong2*)&xsh4[SWZ(2 * r)];       // h0,h1
                    u64        Bx = *(const u64*)&xsh4[SWZ(2 * r + 1)];         // h2
                    #pragma unroll
                    for (int j = 0; j < 4; j++) {
                        const int a = kd - j;
                        if (a < 0 || a > 6) continue;
                        acc[j][0] = ffma2(A.x, c_p.w1p[a * 3 + 1], acc[j][0]);
                        acc[j][0] = ffma2(A.y, c_p.w1p[a * 3 + 2], acc[j][0]);
                        acc[j][1] = ffma2(A.x, c_p.w1p[a * 3 + 0], acc[j][1]);
                        acc[j][1] = ffma2(A.y, c_p.w1p[a * 3 + 1], acc[j][1]);
                        acc[j][1] = ffma2(Bx,  c_p.w1p[a * 3 + 2], acc[j][1]);
                    }
                }
            } else {
                #pragma unroll
                for (int kd = 0; kd < 10; kd++) {
                    const int r = 4 * dp + kd;
                    u64        Ay = ((const u64*)&xsh4[SWZ(2 * r)])[1];          // h1
                    ulonglong2 Bv = *(const ulonglong2*)&xsh4[SWZ(2 * r + 1)];   // h2,h3
                    #pragma unroll
                    for (int j = 0; j < 4; j++) {
                        const int a = kd - j;
                        if (a < 0 || a > 6) continue;
                        acc[j][0] = ffma2(Ay,   c_p.w1p[a * 3 + 0], acc[j][0]);
                        acc[j][0] = ffma2(Bv.x, c_p.w1p[a * 3 + 1], acc[j][0]);
                        acc[j][0] = ffma2(Bv.y, c_p.w1p[a * 3 + 2], acc[j][0]);
                        acc[j][1] = ffma2(Bv.x, c_p.w1p[a * 3 + 0], acc[j][1]);
                        acc[j][1] = ffma2(Bv.y, c_p.w1p[a * 3 + 1], acc[j][1]);
                    }
                }
            }
            float bv0 = -1.f, bv1 = -1.f, bv2 = -1.f, bv3 = -1.f;
            float bj0 = 0.f, bj1 = 0.f, bj2 = 0.f, bj3 = 0.f;   // best j as float
            #pragma unroll
            for (int j = 0; j < 4; j++) {
                const float fj = (float)j;
                float p00, p01, p10, p11, v;
                upk2(acc[j][0], p00, p01); upk2(acc[j][1], p10, p11);
                v = fmaxf(p00, 0.f); if (v > bv0) { bv0 = v; bj0 = fj; }  // strict > = first-max
                v = fmaxf(p01, 0.f); if (v > bv1) { bv1 = v; bj1 = fj; }
                v = fmaxf(p10, 0.f); if (v > bv2) { bv2 = v; bj2 = fj; }
                v = fmaxf(p11, 0.f); if (v > bv3) { bv3 = v; bj3 = fj; }
            }
            p1sh4[SWZ(2 * (dp + 3) + hp)] = make_float4(bv0, bv1, bv2, bv3);
            // index = ((4dp+bj)*4 + h)*2 + w = base + bj*8
            const float cb = (float)(((4 * dp) * 4 + 2 * hp) * 2);
            float4 iv;
            iv.x = fmaf(bj0, 8.f, cb);
            iv.y = fmaf(bj1, 8.f, cb + 1.f);
            iv.z = fmaf(bj2, 8.f, cb + 2.f);
            iv.w = fmaf(bj3, 8.f, cb + 3.f);
            *(float4*)&out[OFF_P1 + (size_t)b * P1N + dp * 8 + hp * 4] = iv;
        }
    }
    __syncthreads();

    // ------- Phase C: conv2(7,3,1)+ReLU+maxpool3+argmax, hp warp-specialized -------
    {
        const int hp = tid >> 5;
        const int dp = tid & 31;
        if (dp < 10) {
            u64 acc[3][2];
            {
                u64 bi = c_p.bb[1];
                #pragma unroll
                for (int j = 0; j < 3; j++) { acc[j][0] = bi; acc[j][1] = bi; }
            }
            if (hp == 0) {
                #pragma unroll
                for (int t = 0; t < 9; t++) {
                    const int r = 3 * dp + t;
                    ulonglong2 A = *(const ulonglong2*)&p1sh4[SWZ(2 * r)];
                    u64        Bx = *(const u64*)&p1sh4[SWZ(2 * r + 1)];
                    #pragma unroll
                    for (int j = 0; j < 3; j++) {
                        const int a = t - j;
                        if (a < 0 || a > 6) continue;
                        acc[j][0] = ffma2(A.x, c_p.w2p[a * 3 + 1], acc[j][0]);
                        acc[j][0] = ffma2(A.y, c_p.w2p[a * 3 + 2], acc[j][0]);
                        acc[j][1] = ffma2(A.x, c_p.w2p[a * 3 + 0], acc[j][1]);
                        acc[j][1] = ffma2(A.y, c_p.w2p[a * 3 + 1], acc[j][1]);
                        acc[j][1] = ffma2(Bx,  c_p.w2p[a * 3 + 2], acc[j][1]);
                    }
                }
            } else {
                #pragma unroll
                for (int t = 0; t < 9; t++) {
                    const int r = 3 * dp + t;
                    u64        Ay = ((const u64*)&p1sh4[SWZ(2 * r)])[1];
                    ulonglong2 Bv = *(const ulonglong2*)&p1sh4[SWZ(2 * r + 1)];
                    #pragma unroll
                    for (int j = 0; j < 3; j++) {
                        const int a = t - j;
                        if (a < 0 || a > 6) continue;
                        acc[j][0] = ffma2(Ay,   c_p.w2p[a * 3 + 0], acc[j][0]);
                        acc[j][0] = ffma2(Bv.x, c_p.w2p[a * 3 + 1], acc[j][0]);
                        acc[j][0] = ffma2(Bv.y, c_p.w2p[a * 3 + 2], acc[j][0]);
                        acc[j][1] = ffma2(Bv.x, c_p.w2p[a * 3 + 0], acc[j][1]);
                        acc[j][1] = ffma2(Bv.y, c_p.w2p[a * 3 + 1], acc[j][1]);
                    }
                }
            }
            float bv0 = -1.f, bv1 = -1.f, bv2 = -1.f, bv3 = -1.f;
            float bj0 = 0.f, bj1 = 0.f, bj2 = 0.f, bj3 = 0.f;
            #pragma unroll
            for (int j = 0; j < 3; j++) {
                const float fj = (float)j;
                float p00, p01, p10, p11, v;
                upk2(acc[j][0], p00, p01); upk2(acc[j][1], p10, p11);
                v = fmaxf(p00, 0.f); if (v > bv0) { bv0 = v; bj0 = fj; }
                v = fmaxf(p01, 0.f); if (v > bv1) { bv1 = v; bj1 = fj; }
                v = fmaxf(p10, 0.f); if (v > bv2) { bv2 = v; bj2 = fj; }
                v = fmaxf(p11, 0.f); if (v > bv3) { bv3 = v; bj3 = fj; }
            }
            *(float4*)&p2v[dp * 8 + hp * 4] = make_float4(bv0, bv1, bv2, bv3);
            const float cb = (float)(((3 * dp) * 4 + 2 * hp) * 2);
            float4 iv;
            iv.x = fmaf(bj0, 8.f, cb);
            iv.y = fmaf(bj1, 8.f, cb + 1.f);
            iv.z = fmaf(bj2, 8.f, cb + 2.f);
            iv.w = fmaf(bj3, 8.f, cb + 3.f);
            *(float4*)&out[OFF_P2 + (size_t)b * P2N + dp * 8 + hp * 4] = iv;
        }
    }
    __syncthreads();

    // ------- Phase E: fcm1 (80->10) + ELU, 4 lanes/output (j=tid>>2, s=tid&3) -------
    if (tid < 40) {
        const int s = tid & 3;
        float acc = 0.0f;
        #pragma unroll
        for (int i = 0; i < 20; i++)
            acc = fmaf(p2v[s + 4 * i], g_fm1Y[40 * i + tid], acc);   // bcast LDS + coalesced LDG
        unsigned m = __activemask();
        acc += __shfl_xor_sync(m, acc, 2);
        acc += __shfl_xor_sync(m, acc, 1);
        if (s == 0) {
            float t = acc + fcm1_b[tid >> 2];
            vec[tid >> 2] = (t > 0.0f) ? t : expm1f(t);
        }
    }
    __syncthreads();

    // ------- Phase F: fc (11->100) + BatchNorm eval, 2 outputs/thread -------
    {
        float acc0 = fc_b[tid];
        float acc1 = (tid < 36) ? fc_b[tid + 64] : 0.0f;
        #pragma unroll
        for (int k = 0; k < 11; k++) {
            float vk = vec[k];                                       // broadcast
            acc0 = fmaf(vk, g_fcX[k * 100 + tid], acc0);
            if (tid < 36) acc1 = fmaf(vk, g_fcX[k * 100 + tid + 64], acc1);
        }
        out[OFF_Z + (size_t)b * NLATENT + tid] = acc0 * 0.9999950000374996f;
        if (tid < 36)
            out[OFF_Z + (size_t)b * NLATENT + tid + 64] = acc1 * 0.9999950000374996f;
    }
}

extern "C" void kernel_launch(void* const* d_in, const int* in_sizes, int n_in,
                              void* d_out, int out_size)
{
    const float* x1     = (const float*)d_in[0];
    const float* x2     = (const float*)d_in[1];
    // d_in[2]=shifts, d_in[3]=nonzero_mask_xm : unused in eval-mode forward
    const float* w1     = (const float*)d_in[4];
    const float* b1     = (const float*)d_in[5];
    const float* w2     = (const float*)d_in[6];
    const float* b2     = (const float*)d_in[7];
    const float* fcm1_w = (const float*)d_in[8];
    const float* fcm1_b = (const float*)d_in[9];
    const float* fc_w   = (const float*)d_in[10];
    const float* fc_b   = (const float*)d_in[11];
    float* out = (float*)d_out;

    prep_kernel<<<1, 128>>>(w1, b1, w2, b2, fcm1_w, fc_w);

    // ONE consolidated D2D memcpy node: staging -> constant bank
    void* stage_ptr = nullptr;
    cudaGetSymbolAddress(&stage_ptr, g_stage);        // host-side lookup, no alloc
    cudaMemcpyToSymbolAsync(c_p, stage_ptr, sizeof(CParams), 0,
                            cudaMemcpyDeviceToDevice, 0);

    enc_kernel<<<B_TOT, 64>>>(x1, x2, fcm1_b, fc_b, out);
}